// round 1
// baseline (speedup 1.0000x reference)
#include <cuda_runtime.h>
#include <math.h>

#define Bq    16
#define Cdim  384
#define Ndim  4096
#define NH    8
#define HD    48
#define OC    1152   // 3*C

// Scratch (allocation-free rule: __device__ globals)
__device__ float g_qkv[(size_t)Bq * Ndim * OC];    // [B*N, 3C] row-major
__device__ float g_attn[(size_t)Bq * Ndim * Cdim]; // [B*N, C]  row-major

// ---------------------------------------------------------------------------
// Kernel 1: qkv = X^T @ W_qkv^T
//   A[m][k] = x[b, k, n]  (m = b*4096+n), W row-major [1152, 384]
//   128x128 tile, BK=8, 8x8 microtile, 256 threads
// ---------------------------------------------------------------------------
__global__ __launch_bounds__(256) void qkv_gemm(const float* __restrict__ x,
                                                const float* __restrict__ w) {
    __shared__ float As[8][128];
    __shared__ float Bs[8][128];
    const int tid = threadIdx.x;
    const int tx = tid & 15, ty = tid >> 4;
    const int row0 = blockIdx.y * 128;      // global token row
    const int b   = row0 >> 12;             // /4096 (tiles never cross batch)
    const int n0  = row0 & 4095;
    const int j0  = blockIdx.x * 128;       // output column (of 1152)
    const float* xb = x + (size_t)b * Cdim * Ndim;

    float acc[8][8];
#pragma unroll
    for (int i = 0; i < 8; i++)
#pragma unroll
        for (int j = 0; j < 8; j++) acc[i][j] = 0.f;

    for (int kt = 0; kt < Cdim; kt += 8) {
        // A tile: As[k][m] = xb[(kt+k)*N + n0+m]  (coalesced float4, no transpose)
        {
            int k  = tid >> 5;            // 0..7
            int mv = (tid & 31) << 2;     // 0..124
            float4 v = *(const float4*)(xb + (size_t)(kt + k) * Ndim + n0 + mv);
            *(float4*)(&As[k][mv]) = v;
        }
        // B tile: Bs[k][j] = w[(j0+j)*C + kt+k]  (float4 along k, scatter-transpose)
        {
            int j  = tid >> 1;            // 0..127
            int k4 = (tid & 1) << 2;      // 0 or 4
            float4 v = *(const float4*)(w + (size_t)(j0 + j) * Cdim + kt + k4);
            Bs[k4 + 0][j] = v.x; Bs[k4 + 1][j] = v.y;
            Bs[k4 + 2][j] = v.z; Bs[k4 + 3][j] = v.w;
        }
        __syncthreads();
#pragma unroll
        for (int k = 0; k < 8; k++) {
            float am[8], bn[8];
            *(float4*)(am)     = *(const float4*)(&As[k][ty * 8]);
            *(float4*)(am + 4) = *(const float4*)(&As[k][ty * 8 + 4]);
            *(float4*)(bn)     = *(const float4*)(&Bs[k][tx * 8]);
            *(float4*)(bn + 4) = *(const float4*)(&Bs[k][tx * 8 + 4]);
#pragma unroll
            for (int i = 0; i < 8; i++)
#pragma unroll
                for (int j = 0; j < 8; j++) acc[i][j] += am[i] * bn[j];
        }
        __syncthreads();
    }
    // Store: rows contiguous in columns -> float4, warp-contiguous
#pragma unroll
    for (int i = 0; i < 8; i++) {
        size_t base = (size_t)(row0 + ty * 8 + i) * OC + j0 + tx * 8;
        *(float4*)(&g_qkv[base])     = make_float4(acc[i][0], acc[i][1], acc[i][2], acc[i][3]);
        *(float4*)(&g_qkv[base + 4]) = make_float4(acc[i][4], acc[i][5], acc[i][6], acc[i][7]);
    }
}

// ---------------------------------------------------------------------------
// Kernel 2: block-local attention. One CTA per (b, head, chunk) = 8192 CTAs.
//   q,k,v tiles [64][48] padded to 49; scores [64][65].
// ---------------------------------------------------------------------------
__global__ __launch_bounds__(256) void attn_kernel() {
    extern __shared__ float sm[];
    float* qs = sm;                 // 64*49
    float* ks = qs + 64 * 49;
    float* vs = ks + 64 * 49;
    float* ss = vs + 64 * 49;       // 64*65
    const int tid = threadIdx.x;
    const int blk = blockIdx.x;
    const int b  = blk >> 9;
    const int h  = (blk >> 6) & 7;
    const int n0 = (blk & 63) << 6;
    const size_t rowbase = ((size_t)b * Ndim + n0) * OC + h * HD;

#pragma unroll
    for (int e = 0; e < 12; e++) {
        int idx = tid + e * 256;          // 0..3071
        int r = idx / 48, d = idx % 48;
        size_t g = rowbase + (size_t)r * OC + d;
        qs[r * 49 + d] = g_qkv[g];
        ks[r * 49 + d] = g_qkv[g + 384];
        vs[r * 49 + d] = g_qkv[g + 768];
    }
    __syncthreads();

    const float scale = 0.14433756729740643f; // 1/sqrt(48)
    // scores: each thread 16 elements of one row
    {
        int r  = tid >> 2;
        int c0 = (tid & 3) << 4;
#pragma unroll
        for (int e = 0; e < 16; e++) {
            int c = c0 + e;
            float s = 0.f;
#pragma unroll
            for (int i = 0; i < 48; i++) s += qs[r * 49 + i] * ks[c * 49 + i];
            ss[r * 65 + c] = s * scale;
        }
    }
    __syncthreads();

    // softmax: warp w owns rows w*8 .. w*8+7 (64 cols = 2 per lane)
    {
        int w = tid >> 5, lane = tid & 31;
        for (int rr = 0; rr < 8; rr++) {
            int r = w * 8 + rr;
            float v0 = ss[r * 65 + lane], v1 = ss[r * 65 + lane + 32];
            float m = fmaxf(v0, v1);
#pragma unroll
            for (int o = 16; o > 0; o >>= 1) m = fmaxf(m, __shfl_xor_sync(0xffffffffu, m, o));
            float e0 = __expf(v0 - m), e1 = __expf(v1 - m);
            float s = e0 + e1;
#pragma unroll
            for (int o = 16; o > 0; o >>= 1) s += __shfl_xor_sync(0xffffffffu, s, o);
            float inv = 1.f / s;
            ss[r * 65 + lane]      = e0 * inv;
            ss[r * 65 + lane + 32] = e1 * inv;
        }
    }
    __syncthreads();

    // out = P @ V, write to g_attn [B*N, C] at column h*48
#pragma unroll
    for (int e = 0; e < 12; e++) {
        int idx = tid + e * 256;
        int r = idx / 48, d = idx % 48;
        float o = 0.f;
#pragma unroll
        for (int k = 0; k < 64; k++) o += ss[r * 65 + k] * vs[k * 49 + d];
        g_attn[((size_t)b * Ndim + n0 + r) * Cdim + h * HD + d] = o;
    }
}

// ---------------------------------------------------------------------------
// Kernel 3: out[b,c,n] = attn[b*N+n][:] . proj_w[c][:] + proj_b[c]
//   Same GEMM shape; output transposed to [B, C, N] with stride-1 stores in n.
// ---------------------------------------------------------------------------
__global__ __launch_bounds__(256) void proj_gemm(const float* __restrict__ w,
                                                 const float* __restrict__ bias,
                                                 float* __restrict__ out) {
    __shared__ float As[8][128];
    __shared__ float Bs[8][128];
    const int tid = threadIdx.x;
    const int tx = tid & 15, ty = tid >> 4;
    const int row0 = blockIdx.y * 128;   // token rows
    const int j0   = blockIdx.x * 128;   // output channel c

    float acc[8][8];
#pragma unroll
    for (int i = 0; i < 8; i++)
#pragma unroll
        for (int j = 0; j < 8; j++) acc[i][j] = 0.f;

    for (int kt = 0; kt < Cdim; kt += 8) {
        // A tile: transpose-on-load from row-major g_attn
        {
            int m  = tid >> 1;
            int k4 = (tid & 1) << 2;
            float4 v = *(const float4*)(&g_attn[(size_t)(row0 + m) * Cdim + kt + k4]);
            As[k4 + 0][m] = v.x; As[k4 + 1][m] = v.y;
            As[k4 + 2][m] = v.z; As[k4 + 3][m] = v.w;
        }
        {
            int j  = tid >> 1;
            int k4 = (tid & 1) << 2;
            float4 v = *(const float4*)(w + (size_t)(j0 + j) * Cdim + kt + k4);
            Bs[k4 + 0][j] = v.x; Bs[k4 + 1][j] = v.y;
            Bs[k4 + 2][j] = v.z; Bs[k4 + 3][j] = v.w;
        }
        __syncthreads();
#pragma unroll
        for (int k = 0; k < 8; k++) {
            float am[8], bn[8];
            // token index from tx -> final stores stride-1 in n
            *(float4*)(am)     = *(const float4*)(&As[k][tx * 8]);
            *(float4*)(am + 4) = *(const float4*)(&As[k][tx * 8 + 4]);
            *(float4*)(bn)     = *(const float4*)(&Bs[k][ty * 8]);
            *(float4*)(bn + 4) = *(const float4*)(&Bs[k][ty * 8 + 4]);
#pragma unroll
            for (int i = 0; i < 8; i++)
#pragma unroll
                for (int j = 0; j < 8; j++) acc[i][j] += am[i] * bn[j];
        }
        __syncthreads();
    }

    const int b  = row0 >> 12;
    const int n0 = (row0 & 4095) + tx * 8;
#pragma unroll
    for (int jj = 0; jj < 8; jj++) {
        int c = j0 + ty * 8 + jj;
        float bi = bias[c];
        size_t base = (size_t)b * Cdim * Ndim + (size_t)c * Ndim + n0;
        *(float4*)(&out[base])     = make_float4(acc[0][jj] + bi, acc[1][jj] + bi,
                                                 acc[2][jj] + bi, acc[3][jj] + bi);
        *(float4*)(&out[base + 4]) = make_float4(acc[4][jj] + bi, acc[5][jj] + bi,
                                                 acc[6][jj] + bi, acc[7][jj] + bi);
    }
}

// ---------------------------------------------------------------------------
extern "C" void kernel_launch(void* const* d_in, const int* in_sizes, int n_in,
                              void* d_out, int out_size) {
    const float* x      = (const float*)d_in[0];
    const float* qkv_w  = (const float*)d_in[1];
    const float* proj_w = (const float*)d_in[2];
    const float* proj_b = (const float*)d_in[3];
    float* out = (float*)d_out;

    const int smem_attn = (3 * 64 * 49 + 64 * 65) * sizeof(float); // 54272 B
    cudaFuncSetAttribute(attn_kernel, cudaFuncAttributeMaxDynamicSharedMemorySize, smem_attn);

    qkv_gemm<<<dim3(9, 512), 256>>>(x, qkv_w);        // [65536,384]@[384,1152]
    attn_kernel<<<8192, 256, smem_attn>>>();          // block-local attention
    proj_gemm<<<dim3(3, 512), 256>>>(proj_w, proj_b, out); // [65536,384]@[384,384]+b
}

// round 3
// speedup vs baseline: 3.6241x; 3.6241x over previous
#include <cuda_runtime.h>
#include <cstdint>

#define Cdim  384
#define Ndim  4096
#define NH    8
#define HD    48
#define OC    1152
#define TOK   65536
#define LDA   36            // smem row stride (floats), conflict-free for STS + LDSM

// Scratch (__device__ globals: allocation-free rule)
__device__ float g_qkvT[(size_t)OC * TOK];     // [3C][tokens]
__device__ float g_attn[(size_t)TOK * Cdim];   // [tokens][C]

// ---------------------------------------------------------------------------
// helpers
// ---------------------------------------------------------------------------
__device__ __forceinline__ float f2tf32(float f) {
    uint32_t r; asm("cvt.rna.tf32.f32 %0, %1;" : "=r"(r) : "f"(f));
    return __uint_as_float(r);
}
__device__ __forceinline__ uint32_t smem_u32(const void* p) {
    uint32_t a; asm("{ .reg .u64 t; cvta.to.shared.u64 t, %1; cvt.u32.u64 %0, t; }" : "=r"(a) : "l"(p));
    return a;
}
__device__ __forceinline__ void ldsm4(uint32_t& r0, uint32_t& r1, uint32_t& r2, uint32_t& r3,
                                      uint32_t addr) {
    asm volatile("ldmatrix.sync.aligned.m8n8.x4.shared.b16 {%0,%1,%2,%3}, [%4];"
                 : "=r"(r0), "=r"(r1), "=r"(r2), "=r"(r3) : "r"(addr));
}
__device__ __forceinline__ void mma_tf32(float* d, const uint32_t* a, const uint32_t* b) {
    asm volatile("mma.sync.aligned.m16n8k8.row.col.f32.tf32.tf32.f32 "
                 "{%0,%1,%2,%3}, {%4,%5,%6,%7}, {%8,%9}, {%0,%1,%2,%3};"
                 : "+f"(d[0]), "+f"(d[1]), "+f"(d[2]), "+f"(d[3])
                 : "r"(a[0]), "r"(a[1]), "r"(a[2]), "r"(a[3]), "r"(b[0]), "r"(b[1]));
}

// 16 mma.sync per k-step x 4 k-steps on one 128x128x32 tile slice (per warp 64x32)
__device__ __forceinline__ void compute_iter(uint32_t sbase, int buf,
                                             const uint32_t offA[4], const uint32_t offB[2],
                                             float acc[4][4][4]) {
    const uint32_t base = sbase + buf * 73728u / 2u;   // 36864 bytes per buffer
#pragma unroll
    for (int ks = 0; ks < 4; ks++) {
        uint32_t a[4][4], bb[2][4];
#pragma unroll
        for (int mt = 0; mt < 4; mt++)
            ldsm4(a[mt][0], a[mt][1], a[mt][2], a[mt][3], base + offA[mt] + ks * 32);
#pragma unroll
        for (int p = 0; p < 2; p++)
            ldsm4(bb[p][0], bb[p][1], bb[p][2], bb[p][3], base + offB[p] + ks * 32);
#pragma unroll
        for (int mt = 0; mt < 4; mt++)
#pragma unroll
            for (int p = 0; p < 2; p++) {
                mma_tf32(acc[mt][2 * p],     a[mt], &bb[p][0]);
                mma_tf32(acc[mt][2 * p + 1], a[mt], &bb[p][2]);
            }
    }
}

// ---------------------------------------------------------------------------
// Kernel 1: g_qkvT[j][tok] = sum_k qkv_w[j][k] * x[b][k][n]
//   A = weights [j][k] (natural), B = tokens [tok][k] (transpose-on-load from x)
// ---------------------------------------------------------------------------
__global__ __launch_bounds__(256) void qkv_mma(const float* __restrict__ x,
                                               const float* __restrict__ w) {
    extern __shared__ float smf[];
    const uint32_t sbase = smem_u32(smf);
    const int tid = threadIdx.x;
    const int lane = tid & 31, wid = tid >> 5;
    const int warp_m = wid >> 2, warp_n = wid & 3;
    const int j0   = blockIdx.x * 128;
    const int tok0 = blockIdx.y * 128;
    const int n0   = tok0 & 4095;
    const float* xb = x + (size_t)(tok0 >> 12) * Cdim * Ndim;

    // ldmatrix per-lane offsets (bytes from buffer base)
    const int a_row = warp_m * 64 + ((lane >> 3) & 1) * 8 + (lane & 7);
    const int a_col = (lane >> 4) * 4;
    const int b_row = warp_n * 32 + (lane >> 4) * 8 + (lane & 7);
    const int b_col = ((lane >> 3) & 1) * 4;
    uint32_t offA[4], offB[2];
#pragma unroll
    for (int mt = 0; mt < 4; mt++) offA[mt] = ((a_row + mt * 16) * LDA + a_col) * 4;
#pragma unroll
    for (int p = 0; p < 2; p++)    offB[p]  = (4608 + (b_row + p * 16) * LDA + b_col) * 4;

    const int tokl  = tid & 127;
    const int khalf = tid >> 7;

    float acc[4][4][4];
#pragma unroll
    for (int i = 0; i < 4; i++)
#pragma unroll
        for (int j = 0; j < 4; j++)
#pragma unroll
            for (int q = 0; q < 4; q++) acc[i][j][q] = 0.f;

    // prologue: tile 0 into buffer 0
    {
        float* bufA = smf;
        float* bufB = smf + 4608;
#pragma unroll
        for (int u = 0; u < 4; u++) {
            int idx = u * 256 + tid, j = idx >> 3, k4 = (idx & 7) * 4;
            float4 v = *(const float4*)(w + (size_t)(j0 + j) * Cdim + k4);
            *(float4*)(bufA + j * LDA + k4) =
                make_float4(f2tf32(v.x), f2tf32(v.y), f2tf32(v.z), f2tf32(v.w));
        }
#pragma unroll
        for (int q = 0; q < 4; q++) {
            float4 c;
            c.x = f2tf32(xb[(size_t)(khalf * 16 + q * 4 + 0) * Ndim + n0 + tokl]);
            c.y = f2tf32(xb[(size_t)(khalf * 16 + q * 4 + 1) * Ndim + n0 + tokl]);
            c.z = f2tf32(xb[(size_t)(khalf * 16 + q * 4 + 2) * Ndim + n0 + tokl]);
            c.w = f2tf32(xb[(size_t)(khalf * 16 + q * 4 + 3) * Ndim + n0 + tokl]);
            *(float4*)(bufB + tokl * LDA + khalf * 16 + q * 4) = c;
        }
    }
    __syncthreads();

    for (int it = 0; it < 12; it++) {
        float4 av[4]; float bv[16];
        if (it < 11) {
            const int kt = (it + 1) * 32;
#pragma unroll
            for (int u = 0; u < 4; u++) {
                int idx = u * 256 + tid;
                av[u] = *(const float4*)(w + (size_t)(j0 + (idx >> 3)) * Cdim + kt + (idx & 7) * 4);
            }
#pragma unroll
            for (int i = 0; i < 16; i++)
                bv[i] = xb[(size_t)(kt + khalf * 16 + i) * Ndim + n0 + tokl];
        }
        compute_iter(sbase, it & 1, offA, offB, acc);
        if (it < 11) {
            float* bufA = smf + ((it + 1) & 1) * 9216;
            float* bufB = bufA + 4608;
#pragma unroll
            for (int u = 0; u < 4; u++) {
                int idx = u * 256 + tid, j = idx >> 3, k4 = (idx & 7) * 4;
                *(float4*)(bufA + j * LDA + k4) =
                    make_float4(f2tf32(av[u].x), f2tf32(av[u].y), f2tf32(av[u].z), f2tf32(av[u].w));
            }
#pragma unroll
            for (int q = 0; q < 4; q++) {
                *(float4*)(bufB + tokl * LDA + khalf * 16 + q * 4) =
                    make_float4(f2tf32(bv[q * 4 + 0]), f2tf32(bv[q * 4 + 1]),
                                f2tf32(bv[q * 4 + 2]), f2tf32(bv[q * 4 + 3]));
            }
        }
        __syncthreads();
    }

    // epilogue: D rows = channels, cols = tokens -> g_qkvT
    const int gid = lane >> 2, tig = lane & 3;
#pragma unroll
    for (int mt = 0; mt < 4; mt++) {
        int r = j0 + warp_m * 64 + mt * 16 + gid;
        size_t r0o = (size_t)r * TOK, r1o = (size_t)(r + 8) * TOK;
        int cbase = tok0 + warp_n * 32 + 2 * tig;
#pragma unroll
        for (int ut = 0; ut < 4; ut++) {
            int c = cbase + ut * 8;
            *(float2*)(&g_qkvT[r0o + c]) = make_float2(acc[mt][ut][0], acc[mt][ut][1]);
            *(float2*)(&g_qkvT[r1o + c]) = make_float2(acc[mt][ut][2], acc[mt][ut][3]);
        }
    }
}

// ---------------------------------------------------------------------------
// Kernel 2: block-local attention (fp32, register-blocked)
// ---------------------------------------------------------------------------
__global__ __launch_bounds__(256) void attn_kernel() {
    extern __shared__ float sm[];
    float* qs = sm;                 // 64 x 49
    float* ks = qs + 64 * 49;
    float* vs = ks + 64 * 49;
    float* ss = vs + 64 * 49;       // 64 x 65
    const int tid = threadIdx.x;
    const int blk = blockIdx.x;
    const int b = blk >> 9;
    const int h = (blk >> 6) & 7;
    const int n0 = (blk & 63) << 6;
    const size_t m0 = (size_t)b * Ndim + n0;
    const float* qT = g_qkvT + (size_t)(h * HD) * TOK + m0;
    const float* kT = qT + (size_t)Cdim * TOK;
    const float* vT = kT + (size_t)Cdim * TOK;

#pragma unroll
    for (int e = 0; e < 12; e++) {
        int idx = e * 256 + tid;
        int d = idx >> 6, r = idx & 63;
        qs[r * 49 + d] = qT[(size_t)d * TOK + r];
        ks[r * 49 + d] = kT[(size_t)d * TOK + r];
        vs[r * 49 + d] = vT[(size_t)d * TOK + r];
    }
    __syncthreads();

    const float scale = 0.14433756729740643f; // 1/sqrt(48)
    {
        const int r0 = (tid >> 4) << 2;
        const int c0 = (tid & 15) << 2;
        float acc[4][4];
#pragma unroll
        for (int i = 0; i < 4; i++)
#pragma unroll
            for (int j = 0; j < 4; j++) acc[i][j] = 0.f;
#pragma unroll 4
        for (int kk = 0; kk < 48; kk++) {
            float qv[4], kv[4];
#pragma unroll
            for (int i = 0; i < 4; i++) qv[i] = qs[(r0 + i) * 49 + kk];
#pragma unroll
            for (int j = 0; j < 4; j++) kv[j] = ks[(c0 + j) * 49 + kk];
#pragma unroll
            for (int i = 0; i < 4; i++)
#pragma unroll
                for (int j = 0; j < 4; j++) acc[i][j] += qv[i] * kv[j];
        }
#pragma unroll
        for (int i = 0; i < 4; i++)
#pragma unroll
            for (int j = 0; j < 4; j++) ss[(r0 + i) * 65 + c0 + j] = acc[i][j] * scale;
    }
    __syncthreads();

    {
        const int w = tid >> 5, lanei = tid & 31;
#pragma unroll
        for (int rr = 0; rr < 8; rr++) {
            int r = w * 8 + rr;
            float v0 = ss[r * 65 + lanei], v1 = ss[r * 65 + lanei + 32];
            float mx = fmaxf(v0, v1);
#pragma unroll
            for (int o = 16; o > 0; o >>= 1) mx = fmaxf(mx, __shfl_xor_sync(~0u, mx, o));
            float e0 = __expf(v0 - mx), e1 = __expf(v1 - mx);
            float s = e0 + e1;
#pragma unroll
            for (int o = 16; o > 0; o >>= 1) s += __shfl_xor_sync(~0u, s, o);
            float inv = 1.f / s;
            ss[r * 65 + lanei] = e0 * inv;
            ss[r * 65 + lanei + 32] = e1 * inv;
        }
    }
    __syncthreads();

    {
        const int r0 = (tid >> 4) << 2;
        const int d0 = (tid & 15) * 3;
        float acc[4][3];
#pragma unroll
        for (int i = 0; i < 4; i++)
#pragma unroll
            for (int j = 0; j < 3; j++) acc[i][j] = 0.f;
#pragma unroll 4
        for (int kk = 0; kk < 64; kk++) {
            float pv[4], vv[3];
#pragma unroll
            for (int i = 0; i < 4; i++) pv[i] = ss[(r0 + i) * 65 + kk];
#pragma unroll
            for (int j = 0; j < 3; j++) vv[j] = vs[kk * 49 + d0 + j];
#pragma unroll
            for (int i = 0; i < 4; i++)
#pragma unroll
                for (int j = 0; j < 3; j++) acc[i][j] += pv[i] * vv[j];
        }
#pragma unroll
        for (int i = 0; i < 4; i++)
#pragma unroll
            for (int j = 0; j < 3; j++)
                g_attn[(m0 + r0 + i) * Cdim + h * HD + d0 + j] = acc[i][j];
    }
}

// ---------------------------------------------------------------------------
// Kernel 3: out[b][c][n] = sum_k g_attn[tok][k] * proj_w[c][k] + bias[c]
//   A = proj_w (natural), B = g_attn (natural)
// ---------------------------------------------------------------------------
__global__ __launch_bounds__(256) void proj_mma(const float* __restrict__ w,
                                                const float* __restrict__ bias,
                                                float* __restrict__ out) {
    extern __shared__ float smf[];
    const uint32_t sbase = smem_u32(smf);
    const int tid = threadIdx.x;
    const int lane = tid & 31, wid = tid >> 5;
    const int warp_m = wid >> 2, warp_n = wid & 3;
    const int j0   = blockIdx.x * 128;
    const int tok0 = blockIdx.y * 128;

    const int a_row = warp_m * 64 + ((lane >> 3) & 1) * 8 + (lane & 7);
    const int a_col = (lane >> 4) * 4;
    const int b_row = warp_n * 32 + (lane >> 4) * 8 + (lane & 7);
    const int b_col = ((lane >> 3) & 1) * 4;
    uint32_t offA[4], offB[2];
#pragma unroll
    for (int mt = 0; mt < 4; mt++) offA[mt] = ((a_row + mt * 16) * LDA + a_col) * 4;
#pragma unroll
    for (int p = 0; p < 2; p++)    offB[p]  = (4608 + (b_row + p * 16) * LDA + b_col) * 4;

    float acc[4][4][4];
#pragma unroll
    for (int i = 0; i < 4; i++)
#pragma unroll
        for (int j = 0; j < 4; j++)
#pragma unroll
            for (int q = 0; q < 4; q++) acc[i][j][q] = 0.f;

    {
        float* bufA = smf;
        float* bufB = smf + 4608;
#pragma unroll
        for (int u = 0; u < 4; u++) {
            int idx = u * 256 + tid, j = idx >> 3, k4 = (idx & 7) * 4;
            float4 v = *(const float4*)(w + (size_t)(j0 + j) * Cdim + k4);
            *(float4*)(bufA + j * LDA + k4) =
                make_float4(f2tf32(v.x), f2tf32(v.y), f2tf32(v.z), f2tf32(v.w));
            float4 t = *(const float4*)(&g_attn[(size_t)(tok0 + j) * Cdim + k4]);
            *(float4*)(bufB + j * LDA + k4) =
                make_float4(f2tf32(t.x), f2tf32(t.y), f2tf32(t.z), f2tf32(t.w));
        }
    }
    __syncthreads();

    for (int it = 0; it < 12; it++) {
        float4 av[4], bv[4];
        if (it < 11) {
            const int kt = (it + 1) * 32;
#pragma unroll
            for (int u = 0; u < 4; u++) {
                int idx = u * 256 + tid, j = idx >> 3, k4 = (idx & 7) * 4;
                av[u] = *(const float4*)(w + (size_t)(j0 + j) * Cdim + kt + k4);
                bv[u] = *(const float4*)(&g_attn[(size_t)(tok0 + j) * Cdim + kt + k4]);
            }
        }
        compute_iter(sbase, it & 1, offA, offB, acc);
        if (it < 11) {
            float* bufA = smf + ((it + 1) & 1) * 9216;
            float* bufB = bufA + 4608;
#pragma unroll
            for (int u = 0; u < 4; u++) {
                int idx = u * 256 + tid, j = idx >> 3, k4 = (idx & 7) * 4;
                *(float4*)(bufA + j * LDA + k4) =
                    make_float4(f2tf32(av[u].x), f2tf32(av[u].y), f2tf32(av[u].z), f2tf32(av[u].w));
                *(float4*)(bufB + j * LDA + k4) =
                    make_float4(f2tf32(bv[u].x), f2tf32(bv[u].y), f2tf32(bv[u].z), f2tf32(bv[u].w));
            }
        }
        __syncthreads();
    }

    // epilogue: rows = out channels, cols = tokens -> out[b][c][n] (+bias)
    const int gid = lane >> 2, tig = lane & 3;
    float* outb = out + (size_t)(tok0 >> 12) * Cdim * Ndim;
    const int nb = (tok0 & 4095) + warp_n * 32 + 2 * tig;
#pragma unroll
    for (int mt = 0; mt < 4; mt++) {
        int r = j0 + warp_m * 64 + mt * 16 + gid;
        float bi0 = __ldg(&bias[r]), bi1 = __ldg(&bias[r + 8]);
#pragma unroll
        for (int ut = 0; ut < 4; ut++) {
            int c = nb + ut * 8;
            *(float2*)(&outb[(size_t)r * Ndim + c]) =
                make_float2(acc[mt][ut][0] + bi0, acc[mt][ut][1] + bi0);
            *(float2*)(&outb[(size_t)(r + 8) * Ndim + c]) =
                make_float2(acc[mt][ut][2] + bi1, acc[mt][ut][3] + bi1);
        }
    }
}

// ---------------------------------------------------------------------------
extern "C" void kernel_launch(void* const* d_in, const int* in_sizes, int n_in,
                              void* d_out, int out_size) {
    const float* x      = (const float*)d_in[0];
    const float* qkv_w  = (const float*)d_in[1];
    const float* proj_w = (const float*)d_in[2];
    const float* proj_b = (const float*)d_in[3];
    float* out = (float*)d_out;

    const int smem_gemm = 73728;                               // 2 x (A+B) buffers
    const int smem_attn = (3 * 64 * 49 + 64 * 65) * sizeof(float); // 54272
    cudaFuncSetAttribute(qkv_mma,  cudaFuncAttributeMaxDynamicSharedMemorySize, smem_gemm);
    cudaFuncSetAttribute(proj_mma, cudaFuncAttributeMaxDynamicSharedMemorySize, smem_gemm);
    cudaFuncSetAttribute(attn_kernel, cudaFuncAttributeMaxDynamicSharedMemorySize, smem_attn);

    qkv_mma<<<dim3(9, 512), 256, smem_gemm>>>(x, qkv_w);
    attn_kernel<<<8192, 256, smem_attn>>>();
    proj_mma<<<dim3(3, 512), 256, smem_gemm>>>(proj_w, proj_b, out);
}

// round 4
// speedup vs baseline: 4.4247x; 1.2209x over previous
#include <cuda_runtime.h>
#include <cstdint>

#define Cdim  384
#define Ndim  4096
#define NH    8
#define HD    48
#define OC    1152
#define TOK   65536

// Scratch (__device__ globals: allocation-free rule)
__device__ float g_qkvT[(size_t)OC * TOK];     // [3C][tokens]
__device__ float g_attn[(size_t)TOK * Cdim];   // [tokens][C]

// ---------------------------------------------------------------------------
// helpers
// ---------------------------------------------------------------------------
__device__ __forceinline__ float f2tf32(float f) {
    uint32_t r; asm("cvt.rna.tf32.f32 %0, %1;" : "=r"(r) : "f"(f));
    return __uint_as_float(r);
}
__device__ __forceinline__ uint32_t smem_u32(const void* p) {
    uint32_t a; asm("{ .reg .u64 t; cvta.to.shared.u64 t, %1; cvt.u32.u64 %0, t; }" : "=r"(a) : "l"(p));
    return a;
}
__device__ __forceinline__ void ldsm4(uint32_t* r, uint32_t addr) {
    asm volatile("ldmatrix.sync.aligned.m8n8.x4.shared.b16 {%0,%1,%2,%3}, [%4];"
                 : "=r"(r[0]), "=r"(r[1]), "=r"(r[2]), "=r"(r[3]) : "r"(addr));
}
__device__ __forceinline__ void mma_tf32(float* d, const uint32_t* a, const uint32_t* b) {
    asm volatile("mma.sync.aligned.m16n8k8.row.col.f32.tf32.tf32.f32 "
                 "{%0,%1,%2,%3}, {%4,%5,%6,%7}, {%8,%9}, {%0,%1,%2,%3};"
                 : "+f"(d[0]), "+f"(d[1]), "+f"(d[2]), "+f"(d[3])
                 : "r"(a[0]), "r"(a[1]), "r"(a[2]), "r"(a[3]), "r"(b[0]), "r"(b[1]));
}
// Swizzled byte offsets (col in floats, col%4==0). 32-float rows / 64-float rows.
__device__ __forceinline__ uint32_t swz32(int row, int colf) {
    return (uint32_t)(row * 128) + (uint32_t)((((colf >> 2) ^ (row & 7)) << 4));
}
__device__ __forceinline__ uint32_t swz64(int row, int colf) {
    return (uint32_t)(row * 256) + (uint32_t)((((colf >> 2) ^ (row & 7)) << 4));
}

// ---------------------------------------------------------------------------
// GEMM core: CTA tile 128x128, BK=32, 4 warps (2x2), warp tile 64x64.
// Smem: bufA at +buf*32768, bufB at +16384+buf*32768. 64KB total.
// ---------------------------------------------------------------------------
struct FragCtx {
    uint32_t aOff[4]; int aXr[4]; int aCh;
    uint32_t bOff[4]; int bXr[4]; int bCh;
};
__device__ __forceinline__ void frag_init(FragCtx& c, int lane, int warp_m, int warp_n) {
    int ar = warp_m * 64 + ((lane >> 3) & 1) * 8 + (lane & 7);
#pragma unroll
    for (int mt = 0; mt < 4; mt++) { int r = ar + mt * 16; c.aOff[mt] = r * 128; c.aXr[mt] = r & 7; }
    c.aCh = (lane >> 4);
    int br = warp_n * 64 + (lane >> 4) * 8 + (lane & 7);
#pragma unroll
    for (int p = 0; p < 4; p++) { int r = br + p * 16; c.bOff[p] = r * 128; c.bXr[p] = r & 7; }
    c.bCh = (lane >> 3) & 1;
}
__device__ __forceinline__ void compute_iter(uint32_t baseA, uint32_t baseB,
                                             const FragCtx& c, float acc[4][8][4]) {
#pragma unroll
    for (int ks = 0; ks < 4; ks++) {
        uint32_t a[4][4], b[4][4];
#pragma unroll
        for (int mt = 0; mt < 4; mt++)
            ldsm4(a[mt], baseA + c.aOff[mt] + (uint32_t)((((c.aCh + 2 * ks) ^ c.aXr[mt]) << 4)));
#pragma unroll
        for (int p = 0; p < 4; p++)
            ldsm4(b[p], baseB + c.bOff[p] + (uint32_t)((((c.bCh + 2 * ks) ^ c.bXr[p]) << 4)));
#pragma unroll
        for (int mt = 0; mt < 4; mt++)
#pragma unroll
            for (int p = 0; p < 4; p++) {
                mma_tf32(acc[mt][2 * p],     a[mt], &b[p][0]);
                mma_tf32(acc[mt][2 * p + 1], a[mt], &b[p][2]);
            }
    }
}

// ---------------------------------------------------------------------------
// Kernel 1: g_qkvT[j][tok] = sum_k qkv_w[j][k] * x[b][k][n]
// ---------------------------------------------------------------------------
__global__ __launch_bounds__(128, 2) void qkv_mma(const float* __restrict__ x,
                                                  const float* __restrict__ w) {
    extern __shared__ float smf[];
    const uint32_t sbase = smem_u32(smf);
    const int tid = threadIdx.x, lane = tid & 31, wid = tid >> 5;
    const int warp_m = wid >> 1, warp_n = wid & 1;
    const int j0 = blockIdx.x * 128;
    const int tok0 = blockIdx.y * 128;
    const int n0 = tok0 & 4095;
    const float* xb = x + (size_t)(tok0 >> 12) * Cdim * Ndim;

    FragCtx fc; frag_init(fc, lane, warp_m, warp_n);
    float acc[4][8][4];
#pragma unroll
    for (int i = 0; i < 4; i++)
#pragma unroll
        for (int j = 0; j < 8; j++)
#pragma unroll
            for (int q = 0; q < 4; q++) acc[i][j][q] = 0.f;

    float4 sa[8]; float sb[32];
    // prologue loads (tile 0)
#pragma unroll
    for (int u = 0; u < 8; u++) {
        int ci = tid + u * 128, row = ci >> 3, ch = ci & 7;
        sa[u] = *(const float4*)(w + (size_t)(j0 + row) * Cdim + ch * 4);
    }
#pragma unroll
    for (int i = 0; i < 32; i++) sb[i] = xb[(size_t)i * Ndim + n0 + tid];
    // STS tile 0
    {
        char* A = (char*)smf; char* B = (char*)smf + 16384;
#pragma unroll
        for (int u = 0; u < 8; u++) {
            int ci = tid + u * 128, row = ci >> 3, ch = ci & 7;
            *(float4*)(A + swz32(row, ch * 4)) =
                make_float4(f2tf32(sa[u].x), f2tf32(sa[u].y), f2tf32(sa[u].z), f2tf32(sa[u].w));
        }
#pragma unroll
        for (int ch = 0; ch < 8; ch++)
            *(float4*)(B + swz32(tid, ch * 4)) =
                make_float4(f2tf32(sb[ch * 4]), f2tf32(sb[ch * 4 + 1]),
                            f2tf32(sb[ch * 4 + 2]), f2tf32(sb[ch * 4 + 3]));
    }
    __syncthreads();

    for (int it = 0; it < 12; it++) {
        if (it < 11) {
            const int kt = (it + 1) * 32;
#pragma unroll
            for (int u = 0; u < 8; u++) {
                int ci = tid + u * 128, row = ci >> 3, ch = ci & 7;
                sa[u] = *(const float4*)(w + (size_t)(j0 + row) * Cdim + kt + ch * 4);
            }
#pragma unroll
            for (int i = 0; i < 32; i++) sb[i] = xb[(size_t)(kt + i) * Ndim + n0 + tid];
        }
        const uint32_t boff = (uint32_t)(it & 1) * 32768u;
        compute_iter(sbase + boff, sbase + boff + 16384u, fc, acc);
        if (it < 11) {
            char* A = (char*)smf + (((it + 1) & 1) * 32768);
            char* B = A + 16384;
#pragma unroll
            for (int u = 0; u < 8; u++) {
                int ci = tid + u * 128, row = ci >> 3, ch = ci & 7;
                *(float4*)(A + swz32(row, ch * 4)) =
                    make_float4(f2tf32(sa[u].x), f2tf32(sa[u].y), f2tf32(sa[u].z), f2tf32(sa[u].w));
            }
#pragma unroll
            for (int ch = 0; ch < 8; ch++)
                *(float4*)(B + swz32(tid, ch * 4)) =
                    make_float4(f2tf32(sb[ch * 4]), f2tf32(sb[ch * 4 + 1]),
                                f2tf32(sb[ch * 4 + 2]), f2tf32(sb[ch * 4 + 3]));
        }
        __syncthreads();
    }

    const int gid = lane >> 2, tig = lane & 3;
#pragma unroll
    for (int mt = 0; mt < 4; mt++) {
        int r = j0 + warp_m * 64 + mt * 16 + gid;
        size_t r0o = (size_t)r * TOK, r1o = (size_t)(r + 8) * TOK;
        int cb = tok0 + warp_n * 64 + 2 * tig;
#pragma unroll
        for (int nt = 0; nt < 8; nt++) {
            int cc = cb + nt * 8;
            *(float2*)(&g_qkvT[r0o + cc]) = make_float2(acc[mt][nt][0], acc[mt][nt][1]);
            *(float2*)(&g_qkvT[r1o + cc]) = make_float2(acc[mt][nt][2], acc[mt][nt][3]);
        }
    }
}

// ---------------------------------------------------------------------------
// Kernel 2: block-local attention on tensor cores. 1 CTA per (b,h,chunk).
// Smem: Q[64x64] @0, K[64x64] @16384, V[48x64] @32768, P[64x64] @45056.
// ---------------------------------------------------------------------------
__global__ __launch_bounds__(128) void attn_mma() {
    extern __shared__ float smf[];
    const uint32_t sbase = smem_u32(smf);
    const int tid = threadIdx.x, lane = tid & 31, w = tid >> 5;
    const int blk = blockIdx.x;
    const int b = blk >> 9, h = (blk >> 6) & 7, nc = blk & 63;
    const size_t m0 = (size_t)b * Ndim + nc * 64;
    const float* qT = g_qkvT + (size_t)(h * HD) * TOK + m0;
    const float* kT = qT + (size_t)Cdim * TOK;
    const float* vT = kT + (size_t)Cdim * TOK;
    char* Qs = (char*)smf;
    char* Ks = (char*)smf + 16384;
    char* Vs = (char*)smf + 32768;
    char* Ps = (char*)smf + 45056;

    // load Q,K transposed ([tok][k]) and V direct ([d][tok]), cvt to tf32
    {
        const int tok = tid & 63, kh = tid >> 6;
#pragma unroll
        for (int i = 0; i < 24; i++) {
            int k = kh * 24 + i;
            *(float*)(Qs + swz64(tok, k & ~3) + (k & 3) * 4) = f2tf32(qT[(size_t)k * TOK + tok]);
            *(float*)(Ks + swz64(tok, k & ~3) + (k & 3) * 4) = f2tf32(kT[(size_t)k * TOK + tok]);
        }
#pragma unroll
        for (int jv = 0; jv < 6; jv++) {
            int idx = tid + jv * 128;           // 0..767
            int vr = idx >> 4, ch = idx & 15;
            float4 v = *(const float4*)(vT + (size_t)vr * TOK + ch * 4);
            *(float4*)(Vs + swz64(vr, ch * 4)) =
                make_float4(f2tf32(v.x), f2tf32(v.y), f2tf32(v.z), f2tf32(v.w));
        }
    }
    __syncthreads();

    // per-lane fragment geometry
    const int a_row = w * 16 + ((lane >> 3) & 1) * 8 + (lane & 7);
    const uint32_t aOff = a_row * 256; const int aXr = a_row & 7, aCh = (lane >> 4);
    int bRow[4], bXr[4];
#pragma unroll
    for (int p = 0; p < 4; p++) { bRow[p] = p * 16 + (lane >> 4) * 8 + (lane & 7); bXr[p] = bRow[p] & 7; }
    const int bCh = (lane >> 3) & 1;

    // S = Q @ K^T  (m16 rows per warp, n64, k48)
    float s[8][4];
#pragma unroll
    for (int j = 0; j < 8; j++)
#pragma unroll
        for (int q = 0; q < 4; q++) s[j][q] = 0.f;
#pragma unroll
    for (int ks = 0; ks < 6; ks++) {
        uint32_t a[4], kb[4][4];
        ldsm4(a, sbase + aOff + (uint32_t)(((aCh + 2 * ks) ^ aXr) << 4));
#pragma unroll
        for (int p = 0; p < 4; p++)
            ldsm4(kb[p], sbase + 16384u + (uint32_t)(bRow[p] * 256) +
                          (uint32_t)(((bCh + 2 * ks) ^ bXr[p]) << 4));
#pragma unroll
        for (int p = 0; p < 4; p++) {
            mma_tf32(s[2 * p],     a, &kb[p][0]);
            mma_tf32(s[2 * p + 1], a, &kb[p][2]);
        }
    }

    // softmax over 64 cols; lane holds rows (gid, gid+8), cols nt*8 + tig*2 + {0,1}
    const int gid = lane >> 2, tig = lane & 3;
    const float scale = 0.14433756729740643f;
    {
        float m0v = -1e30f, m1v = -1e30f;
#pragma unroll
        for (int nt = 0; nt < 8; nt++) {
#pragma unroll
            for (int q = 0; q < 4; q++) s[nt][q] *= scale;
            m0v = fmaxf(m0v, fmaxf(s[nt][0], s[nt][1]));
            m1v = fmaxf(m1v, fmaxf(s[nt][2], s[nt][3]));
        }
#pragma unroll
        for (int o = 1; o <= 2; o <<= 1) {
            m0v = fmaxf(m0v, __shfl_xor_sync(~0u, m0v, o));
            m1v = fmaxf(m1v, __shfl_xor_sync(~0u, m1v, o));
        }
        float s0 = 0.f, s1 = 0.f;
#pragma unroll
        for (int nt = 0; nt < 8; nt++) {
            s[nt][0] = __expf(s[nt][0] - m0v); s[nt][1] = __expf(s[nt][1] - m0v);
            s[nt][2] = __expf(s[nt][2] - m1v); s[nt][3] = __expf(s[nt][3] - m1v);
            s0 += s[nt][0] + s[nt][1]; s1 += s[nt][2] + s[nt][3];
        }
#pragma unroll
        for (int o = 1; o <= 2; o <<= 1) {
            s0 += __shfl_xor_sync(~0u, s0, o);
            s1 += __shfl_xor_sync(~0u, s1, o);
        }
        float i0 = 1.f / s0, i1 = 1.f / s1;
        const int r0 = w * 16 + gid, r1 = r0 + 8;
#pragma unroll
        for (int nt = 0; nt < 8; nt++) {
            int col = nt * 8 + tig * 2;
            *(float2*)(Ps + swz64(r0, col & ~3) + (col & 3) * 4) =
                make_float2(f2tf32(s[nt][0] * i0), f2tf32(s[nt][1] * i0));
            *(float2*)(Ps + swz64(r1, col & ~3) + (col & 3) * 4) =
                make_float2(f2tf32(s[nt][2] * i1), f2tf32(s[nt][3] * i1));
        }
    }
    __syncwarp();

    // O = P @ V  (m16, n48, k64)
    float o[6][4];
#pragma unroll
    for (int j = 0; j < 6; j++)
#pragma unroll
        for (int q = 0; q < 4; q++) o[j][q] = 0.f;
#pragma unroll
    for (int ks = 0; ks < 8; ks++) {
        uint32_t a[4], vb[3][4];
        ldsm4(a, sbase + 45056u + aOff + (uint32_t)(((aCh + 2 * ks) ^ aXr) << 4));
#pragma unroll
        for (int p = 0; p < 3; p++)
            ldsm4(vb[p], sbase + 32768u + (uint32_t)(bRow[p] * 256) +
                          (uint32_t)(((bCh + 2 * ks) ^ bXr[p]) << 4));
#pragma unroll
        for (int p = 0; p < 3; p++) {
            mma_tf32(o[2 * p],     a, &vb[p][0]);
            mma_tf32(o[2 * p + 1], a, &vb[p][2]);
        }
    }
    // store to g_attn [tok][C]
    {
        const int r0 = w * 16 + gid;
#pragma unroll
        for (int nt = 0; nt < 6; nt++) {
            int col = h * HD + nt * 8 + tig * 2;
            *(float2*)(&g_attn[(m0 + r0) * Cdim + col])     = make_float2(o[nt][0], o[nt][1]);
            *(float2*)(&g_attn[(m0 + r0 + 8) * Cdim + col]) = make_float2(o[nt][2], o[nt][3]);
        }
    }
}

// ---------------------------------------------------------------------------
// Kernel 3: out[b][c][n] = sum_k proj_w[c][k] * g_attn[tok][k] + bias[c]
// ---------------------------------------------------------------------------
__global__ __launch_bounds__(128, 2) void proj_mma(const float* __restrict__ w,
                                                   const float* __restrict__ bias,
                                                   float* __restrict__ out) {
    extern __shared__ float smf[];
    const uint32_t sbase = smem_u32(smf);
    const int tid = threadIdx.x, lane = tid & 31, wid = tid >> 5;
    const int warp_m = wid >> 1, warp_n = wid & 1;
    const int j0 = blockIdx.x * 128;
    const int tok0 = blockIdx.y * 128;

    FragCtx fc; frag_init(fc, lane, warp_m, warp_n);
    float acc[4][8][4];
#pragma unroll
    for (int i = 0; i < 4; i++)
#pragma unroll
        for (int j = 0; j < 8; j++)
#pragma unroll
            for (int q = 0; q < 4; q++) acc[i][j][q] = 0.f;

    float4 sa[8], sb[8];
#pragma unroll
    for (int u = 0; u < 8; u++) {
        int ci = tid + u * 128, row = ci >> 3, ch = ci & 7;
        sa[u] = *(const float4*)(w + (size_t)(j0 + row) * Cdim + ch * 4);
        sb[u] = *(const float4*)(&g_attn[(size_t)(tok0 + row) * Cdim + ch * 4]);
    }
    {
        char* A = (char*)smf; char* B = (char*)smf + 16384;
#pragma unroll
        for (int u = 0; u < 8; u++) {
            int ci = tid + u * 128, row = ci >> 3, ch = ci & 7;
            *(float4*)(A + swz32(row, ch * 4)) =
                make_float4(f2tf32(sa[u].x), f2tf32(sa[u].y), f2tf32(sa[u].z), f2tf32(sa[u].w));
            *(float4*)(B + swz32(row, ch * 4)) =
                make_float4(f2tf32(sb[u].x), f2tf32(sb[u].y), f2tf32(sb[u].z), f2tf32(sb[u].w));
        }
    }
    __syncthreads();

    for (int it = 0; it < 12; it++) {
        if (it < 11) {
            const int kt = (it + 1) * 32;
#pragma unroll
            for (int u = 0; u < 8; u++) {
                int ci = tid + u * 128, row = ci >> 3, ch = ci & 7;
                sa[u] = *(const float4*)(w + (size_t)(j0 + row) * Cdim + kt + ch * 4);
                sb[u] = *(const float4*)(&g_attn[(size_t)(tok0 + row) * Cdim + kt + ch * 4]);
            }
        }
        const uint32_t boff = (uint32_t)(it & 1) * 32768u;
        compute_iter(sbase + boff, sbase + boff + 16384u, fc, acc);
        if (it < 11) {
            char* A = (char*)smf + (((it + 1) & 1) * 32768);
            char* B = A + 16384;
#pragma unroll
            for (int u = 0; u < 8; u++) {
                int ci = tid + u * 128, row = ci >> 3, ch = ci & 7;
                *(float4*)(A + swz32(row, ch * 4)) =
                    make_float4(f2tf32(sa[u].x), f2tf32(sa[u].y), f2tf32(sa[u].z), f2tf32(sa[u].w));
                *(float4*)(B + swz32(row, ch * 4)) =
                    make_float4(f2tf32(sb[u].x), f2tf32(sb[u].y), f2tf32(sb[u].z), f2tf32(sb[u].w));
            }
        }
        __syncthreads();
    }

    const int gid = lane >> 2, tig = lane & 3;
    float* outb = out + (size_t)(tok0 >> 12) * Cdim * Ndim;
    const int nb = (tok0 & 4095) + warp_n * 64 + 2 * tig;
#pragma unroll
    for (int mt = 0; mt < 4; mt++) {
        int r = j0 + warp_m * 64 + mt * 16 + gid;
        float bi0 = __ldg(&bias[r]), bi1 = __ldg(&bias[r + 8]);
#pragma unroll
        for (int nt = 0; nt < 8; nt++) {
            int cc = nb + nt * 8;
            *(float2*)(&outb[(size_t)r * Ndim + cc]) =
                make_float2(acc[mt][nt][0] + bi0, acc[mt][nt][1] + bi0);
            *(float2*)(&outb[(size_t)(r + 8) * Ndim + cc]) =
                make_float2(acc[mt][nt][2] + bi1, acc[mt][nt][3] + bi1);
        }
    }
}

// ---------------------------------------------------------------------------
extern "C" void kernel_launch(void* const* d_in, const int* in_sizes, int n_in,
                              void* d_out, int out_size) {
    const float* x      = (const float*)d_in[0];
    const float* qkv_w  = (const float*)d_in[1];
    const float* proj_w = (const float*)d_in[2];
    const float* proj_b = (const float*)d_in[3];
    float* out = (float*)d_out;

    const int smem_gemm = 65536;
    const int smem_attn = 61440;   // Q16K + K16K + V12K + P16K
    cudaFuncSetAttribute(qkv_mma,  cudaFuncAttributeMaxDynamicSharedMemorySize, smem_gemm);
    cudaFuncSetAttribute(proj_mma, cudaFuncAttributeMaxDynamicSharedMemorySize, smem_gemm);
    cudaFuncSetAttribute(attn_mma, cudaFuncAttributeMaxDynamicSharedMemorySize, smem_attn);

    qkv_mma<<<dim3(9, 512), 128, smem_gemm>>>(x, qkv_w);
    attn_mma<<<8192, 128, smem_attn>>>();
    proj_mma<<<dim3(3, 512), 128, smem_gemm>>>(proj_w, proj_b, out);
}

// round 6
// speedup vs baseline: 6.5036x; 1.4698x over previous
#include <cuda_runtime.h>
#include <cuda_fp16.h>
#include <cstdint>

#define Cdim  384
#define Ndim  4096
#define NH    8
#define HD    48
#define OC    1152
#define TOK   65536

// Scratch (__device__ globals: allocation-free rule) — fp16 now
__device__ __half g_qkvT[(size_t)OC * TOK];     // [3C][tokens]
__device__ __half g_attn[(size_t)TOK * Cdim];   // [tokens][C]

// ---------------------------------------------------------------------------
// helpers
// ---------------------------------------------------------------------------
__device__ __forceinline__ uint32_t smem_u32(const void* p) {
    uint32_t a; asm("{ .reg .u64 t; cvta.to.shared.u64 t, %1; cvt.u32.u64 %0, t; }" : "=r"(a) : "l"(p));
    return a;
}
__device__ __forceinline__ void ldsm4(uint32_t* r, uint32_t addr) {
    asm volatile("ldmatrix.sync.aligned.m8n8.x4.shared.b16 {%0,%1,%2,%3}, [%4];"
                 : "=r"(r[0]), "=r"(r[1]), "=r"(r[2]), "=r"(r[3]) : "r"(addr));
}
__device__ __forceinline__ void ldsm4t(uint32_t* r, uint32_t addr) {
    asm volatile("ldmatrix.sync.aligned.m8n8.x4.trans.shared.b16 {%0,%1,%2,%3}, [%4];"
                 : "=r"(r[0]), "=r"(r[1]), "=r"(r[2]), "=r"(r[3]) : "r"(addr));
}
__device__ __forceinline__ void mma_f16(float* d, const uint32_t* a, const uint32_t b0,
                                        const uint32_t b1) {
    asm volatile("mma.sync.aligned.m16n8k16.row.col.f32.f16.f16.f32 "
                 "{%0,%1,%2,%3}, {%4,%5,%6,%7}, {%8,%9}, {%0,%1,%2,%3};"
                 : "+f"(d[0]), "+f"(d[1]), "+f"(d[2]), "+f"(d[3])
                 : "r"(a[0]), "r"(a[1]), "r"(a[2]), "r"(a[3]), "r"(b0), "r"(b1));
}
// swizzled byte addr for 128B rows (8 x 16B chunks) and 256B rows (16 chunks)
__device__ __forceinline__ uint32_t sw128r(int row, int chunk) {
    return (uint32_t)(row * 128 + ((chunk ^ (row & 7)) << 4));
}
__device__ __forceinline__ uint32_t sw256r(int row, int chunk) {
    return (uint32_t)(row * 256 + ((chunk ^ (row & 7)) << 4));
}
__device__ __forceinline__ uint32_t pack2(float x, float y) {
    uint32_t r;
    asm("cvt.rn.f16x2.f32 %0, %1, %2;" : "=r"(r) : "f"(y), "f"(x));
    return r;
}

// ---------------------------------------------------------------------------
// Kernel 1: g_qkvT[j][tok] = sum_k qkv_w[j][k] * x[b][k][n]   (fp16 mma, BK=64)
// CTA 128 thr, tile 128x128, warps 2x2, warp tile 64x64. A=[j][k] smem 128B rows;
// B=[k][tok] smem 256B rows, transposed in ldmatrix.trans.
// ---------------------------------------------------------------------------
__global__ __launch_bounds__(128, 2) void qkv_mma(const float* __restrict__ x,
                                                  const float* __restrict__ w) {
    extern __shared__ char smem[];
    const uint32_t sbase = smem_u32(smem);
    const int tid = threadIdx.x, lane = tid & 31, wid = tid >> 5;
    const int warp_m = wid >> 1, warp_n = wid & 1;
    const int j0 = blockIdx.x * 128;
    const int tok0 = blockIdx.y * 128;
    const int n0 = tok0 & 4095;
    const float* xb = x + (size_t)(tok0 >> 12) * Cdim * Ndim;

    // fragment address components
    const int aRowL = ((lane >> 3) & 1) * 8 + (lane & 7);
    const int ldCh = lane >> 4;
    int aRow[4];
#pragma unroll
    for (int mt = 0; mt < 4; mt++) aRow[mt] = warp_m * 64 + mt * 16 + aRowL;

    float acc[4][8][4];
#pragma unroll
    for (int i = 0; i < 4; i++)
#pragma unroll
        for (int j = 0; j < 8; j++)
#pragma unroll
            for (int q = 0; q < 4; q++) acc[i][j][q] = 0.f;

    uint2 sa[16], sb[16];

    // ---- prologue: tile 0 ----
#pragma unroll
    for (int u = 0; u < 16; u++) {
        int idx = tid + u * 128;
        int row = idx >> 4, f4 = idx & 15;
        float4 v = *(const float4*)(w + (size_t)(j0 + row) * Cdim + f4 * 4);
        sa[u] = make_uint2(pack2(v.x, v.y), pack2(v.z, v.w));
        int krow = idx >> 5, tf4 = idx & 31;
        float4 t = *(const float4*)(xb + (size_t)krow * Ndim + n0 + tf4 * 4);
        sb[u] = make_uint2(pack2(t.x, t.y), pack2(t.z, t.w));
    }
    {
        char* A = smem; char* B = smem + 16384;
#pragma unroll
        for (int u = 0; u < 16; u++) {
            int idx = tid + u * 128;
            int row = idx >> 4, f4 = idx & 15;
            *(uint2*)(A + sw128r(row, f4 >> 1) + (f4 & 1) * 8) = sa[u];
            int krow = idx >> 5, tf4 = idx & 31;
            *(uint2*)(B + sw256r(krow, tf4 >> 1) + (tf4 & 1) * 8) = sb[u];
        }
    }
    __syncthreads();

    for (int it = 0; it < 6; it++) {
        if (it < 5) {
            const int kt = (it + 1) * 64;
#pragma unroll
            for (int u = 0; u < 16; u++) {
                int idx = tid + u * 128;
                int row = idx >> 4, f4 = idx & 15;
                float4 v = *(const float4*)(w + (size_t)(j0 + row) * Cdim + kt + f4 * 4);
                sa[u] = make_uint2(pack2(v.x, v.y), pack2(v.z, v.w));
                int krow = idx >> 5, tf4 = idx & 31;
                float4 t = *(const float4*)(xb + (size_t)(kt + krow) * Ndim + n0 + tf4 * 4);
                sb[u] = make_uint2(pack2(t.x, t.y), pack2(t.z, t.w));
            }
        }
        // ---- compute on buffer it&1 ----
        {
            const uint32_t bA = sbase + (uint32_t)(it & 1) * 32768u;
            const uint32_t bB = bA + 16384u;
#pragma unroll
            for (int ks = 0; ks < 4; ks++) {
                uint32_t a[4][4], b[4][4];
#pragma unroll
                for (int mt = 0; mt < 4; mt++)
                    ldsm4(a[mt], bA + sw128r(aRow[mt], ks * 2 + ldCh));
#pragma unroll
                for (int p = 0; p < 4; p++) {
                    int krow = ks * 16 + aRowL;
                    int tchunk = warp_n * 8 + p * 2 + ldCh;
                    ldsm4t(b[p], bB + sw256r(krow, tchunk));
                }
#pragma unroll
                for (int mt = 0; mt < 4; mt++)
#pragma unroll
                    for (int p = 0; p < 4; p++) {
                        mma_f16(acc[mt][2 * p],     a[mt], b[p][0], b[p][1]);
                        mma_f16(acc[mt][2 * p + 1], a[mt], b[p][2], b[p][3]);
                    }
            }
        }
        if (it < 5) {
            char* A = smem + (((it + 1) & 1) * 32768);
            char* B = A + 16384;
#pragma unroll
            for (int u = 0; u < 16; u++) {
                int idx = tid + u * 128;
                int row = idx >> 4, f4 = idx & 15;
                *(uint2*)(A + sw128r(row, f4 >> 1) + (f4 & 1) * 8) = sa[u];
                int krow = idx >> 5, tf4 = idx & 31;
                *(uint2*)(B + sw256r(krow, tf4 >> 1) + (tf4 & 1) * 8) = sb[u];
            }
        }
        __syncthreads();
    }

    // epilogue: rows = channels, cols = tokens; fp32 acc -> half2 stores
    const int gid = lane >> 2, tig = lane & 3;
#pragma unroll
    for (int mt = 0; mt < 4; mt++) {
        int r = j0 + warp_m * 64 + mt * 16 + gid;
        size_t r0o = (size_t)r * TOK, r1o = (size_t)(r + 8) * TOK;
        int cb = tok0 + warp_n * 64 + 2 * tig;
#pragma unroll
        for (int nt = 0; nt < 8; nt++) {
            int cc = cb + nt * 8;
            *(uint32_t*)(&g_qkvT[r0o + cc]) = pack2(acc[mt][nt][0], acc[mt][nt][1]);
            *(uint32_t*)(&g_qkvT[r1o + cc]) = pack2(acc[mt][nt][2], acc[mt][nt][3]);
        }
    }
}

// ---------------------------------------------------------------------------
// Kernel 2: block-local attention, fp16 mma. 1 CTA (128 thr) per (b,h,chunk).
// Smem (half): Qs[48][64]@0, Ks[48][64]@6144, Vs[48][64]@12288, Ps[64][64]@18432.
// ---------------------------------------------------------------------------
__global__ __launch_bounds__(128) void attn_mma() {
    extern __shared__ char smem[];
    const uint32_t sbase = smem_u32(smem);
    const int tid = threadIdx.x, lane = tid & 31, w = tid >> 5;
    const int blk = blockIdx.x;
    const int b = blk >> 9, h = (blk >> 6) & 7, nc = blk & 63;
    const size_t m0 = (size_t)b * Ndim + nc * 64;
    const __half* qg = g_qkvT + (size_t)(h * HD) * TOK + m0;

    // fill Q,K,V tiles [d(48)][tok(64)] halves, rows 128B, swizzled; int4 copies
#pragma unroll
    for (int t = 0; t < 3; t++) {
        const __half* src = qg + (size_t)t * Cdim * TOK;
        char* dst = smem + t * 6144;
#pragma unroll
        for (int e = 0; e < 3; e++) {
            int idx = tid + e * 128;           // 0..383
            int row = idx >> 3, ch = idx & 7;
            *(int4*)(dst + sw128r(row, ch)) =
                *(const int4*)(src + (size_t)row * TOK + ch * 8);
        }
    }
    __syncthreads();

    const int aRowL = ((lane >> 3) & 1) * 8 + (lane & 7);
    const int ldCh = lane >> 4;

    // S = Q @ K^T : m16 per warp, n64, k48 (3 ksteps)
    float s[8][4];
#pragma unroll
    for (int j = 0; j < 8; j++)
#pragma unroll
        for (int q = 0; q < 4; q++) s[j][q] = 0.f;
#pragma unroll
    for (int ks = 0; ks < 3; ks++) {
        uint32_t ar[4], a[4], kb[4][4];
        int drow = ks * 16 + aRowL;
        ldsm4t(ar, sbase + sw128r(drow, w * 2 + ldCh));           // Qs
        a[0] = ar[0]; a[1] = ar[2]; a[2] = ar[1]; a[3] = ar[3];   // trans reorder
#pragma unroll
        for (int p = 0; p < 4; p++)
            ldsm4t(kb[p], sbase + 6144u + sw128r(drow, p * 2 + ldCh));
#pragma unroll
        for (int p = 0; p < 4; p++) {
            mma_f16(s[2 * p],     a, kb[p][0], kb[p][1]);
            mma_f16(s[2 * p + 1], a, kb[p][2], kb[p][3]);
        }
    }

    // softmax: lane holds rows (r0, r0+8), cols nt*8 + tig*2 + {0,1}
    const int gid = lane >> 2, tig = lane & 3;
    const float scale = 0.14433756729740643f;   // 1/sqrt(48)
    {
        float m0v = -1e30f, m1v = -1e30f;
#pragma unroll
        for (int nt = 0; nt < 8; nt++) {
#pragma unroll
            for (int q = 0; q < 4; q++) s[nt][q] *= scale;
            m0v = fmaxf(m0v, fmaxf(s[nt][0], s[nt][1]));
            m1v = fmaxf(m1v, fmaxf(s[nt][2], s[nt][3]));
        }
#pragma unroll
        for (int o = 1; o <= 2; o <<= 1) {
            m0v = fmaxf(m0v, __shfl_xor_sync(~0u, m0v, o));
            m1v = fmaxf(m1v, __shfl_xor_sync(~0u, m1v, o));
        }
        float s0 = 0.f, s1 = 0.f;
#pragma unroll
        for (int nt = 0; nt < 8; nt++) {
            s[nt][0] = __expf(s[nt][0] - m0v); s[nt][1] = __expf(s[nt][1] - m0v);
            s[nt][2] = __expf(s[nt][2] - m1v); s[nt][3] = __expf(s[nt][3] - m1v);
            s0 += s[nt][0] + s[nt][1]; s1 += s[nt][2] + s[nt][3];
        }
#pragma unroll
        for (int o = 1; o <= 2; o <<= 1) {
            s0 += __shfl_xor_sync(~0u, s0, o);
            s1 += __shfl_xor_sync(~0u, s1, o);
        }
        float i0 = 1.f / s0, i1 = 1.f / s1;
        const int r0 = w * 16 + gid, r1 = r0 + 8;
        char* Ps = smem + 18432;
#pragma unroll
        for (int nt = 0; nt < 8; nt++) {
            *(uint32_t*)(Ps + sw128r(r0, nt) + tig * 4) = pack2(s[nt][0] * i0, s[nt][1] * i0);
            *(uint32_t*)(Ps + sw128r(r1, nt) + tig * 4) = pack2(s[nt][2] * i1, s[nt][3] * i1);
        }
    }
    __syncwarp();

    // O = P @ V : m16, n48, k64 (4 ksteps). A = Ps [q][ktok]; B = Vs [d][ktok].
    float o[6][4];
#pragma unroll
    for (int j = 0; j < 6; j++)
#pragma unroll
        for (int q = 0; q < 4; q++) o[j][q] = 0.f;
#pragma unroll
    for (int ks = 0; ks < 4; ks++) {
        uint32_t a[4], vb[3][4];
        ldsm4(a, sbase + 18432u + sw128r(w * 16 + aRowL, ks * 2 + ldCh));
#pragma unroll
        for (int p = 0; p < 3; p++)
            ldsm4(vb[p], sbase + 12288u + sw128r(p * 16 + aRowL, ks * 2 + ldCh));
#pragma unroll
        for (int p = 0; p < 3; p++) {
            mma_f16(o[2 * p],     a, vb[p][0], vb[p][2]);
            mma_f16(o[2 * p + 1], a, vb[p][1], vb[p][3]);
        }
    }
    // store O -> g_attn [tok][C] (half2)
    {
        const int r0 = w * 16 + gid;
#pragma unroll
        for (int nt = 0; nt < 6; nt++) {
            int col = h * HD + nt * 8 + tig * 2;
            *(uint32_t*)(&g_attn[(m0 + r0) * Cdim + col])     = pack2(o[nt][0], o[nt][1]);
            *(uint32_t*)(&g_attn[(m0 + r0 + 8) * Cdim + col]) = pack2(o[nt][2], o[nt][3]);
        }
    }
}

// ---------------------------------------------------------------------------
// Kernel 3: out[b][c][n] = sum_k proj_w[c][k] * g_attn[tok][k] + bias[c]
// A = proj_w [c][k] (cvt fp32->half), B = g_attn [tok][k] (already half).
// ---------------------------------------------------------------------------
__global__ __launch_bounds__(128, 2) void proj_mma(const float* __restrict__ w,
                                                   const float* __restrict__ bias,
                                                   float* __restrict__ out) {
    extern __shared__ char smem[];
    const uint32_t sbase = smem_u32(smem);
    const int tid = threadIdx.x, lane = tid & 31, wid = tid >> 5;
    const int warp_m = wid >> 1, warp_n = wid & 1;
    const int j0 = blockIdx.x * 128;
    const int tok0 = blockIdx.y * 128;

    const int aRowL = ((lane >> 3) & 1) * 8 + (lane & 7);
    const int ldCh = lane >> 4;
    int aRow[4], bRow[4];
#pragma unroll
    for (int mt = 0; mt < 4; mt++) aRow[mt] = warp_m * 64 + mt * 16 + aRowL;
#pragma unroll
    for (int p = 0; p < 4; p++)    bRow[p] = warp_n * 64 + p * 16 + aRowL;

    float acc[4][8][4];
#pragma unroll
    for (int i = 0; i < 4; i++)
#pragma unroll
        for (int j = 0; j < 8; j++)
#pragma unroll
            for (int q = 0; q < 4; q++) acc[i][j][q] = 0.f;

    uint2 sa[16]; int4 sb[8];
    // prologue tile 0
#pragma unroll
    for (int u = 0; u < 16; u++) {
        int idx = tid + u * 128, row = idx >> 4, f4 = idx & 15;
        float4 v = *(const float4*)(w + (size_t)(j0 + row) * Cdim + f4 * 4);
        sa[u] = make_uint2(pack2(v.x, v.y), pack2(v.z, v.w));
    }
#pragma unroll
    for (int u = 0; u < 8; u++) {
        int idx = tid + u * 128, row = idx >> 3, ch = idx & 7;
        sb[u] = *(const int4*)(&g_attn[(size_t)(tok0 + row) * Cdim + ch * 8]);
    }
    {
        char* A = smem; char* B = smem + 16384;
#pragma unroll
        for (int u = 0; u < 16; u++) {
            int idx = tid + u * 128, row = idx >> 4, f4 = idx & 15;
            *(uint2*)(A + sw128r(row, f4 >> 1) + (f4 & 1) * 8) = sa[u];
        }
#pragma unroll
        for (int u = 0; u < 8; u++) {
            int idx = tid + u * 128, row = idx >> 3, ch = idx & 7;
            *(int4*)(B + sw128r(row, ch)) = sb[u];
        }
    }
    __syncthreads();

    for (int it = 0; it < 6; it++) {
        if (it < 5) {
            const int kt = (it + 1) * 64;
#pragma unroll
            for (int u = 0; u < 16; u++) {
                int idx = tid + u * 128, row = idx >> 4, f4 = idx & 15;
                float4 v = *(const float4*)(w + (size_t)(j0 + row) * Cdim + kt + f4 * 4);
                sa[u] = make_uint2(pack2(v.x, v.y), pack2(v.z, v.w));
            }
#pragma unroll
            for (int u = 0; u < 8; u++) {
                int idx = tid + u * 128, row = idx >> 3, ch = idx & 7;
                sb[u] = *(const int4*)(&g_attn[(size_t)(tok0 + row) * Cdim + kt + ch * 8]);
            }
        }
        {
            const uint32_t bA = sbase + (uint32_t)(it & 1) * 32768u;
            const uint32_t bB = bA + 16384u;
#pragma unroll
            for (int ks = 0; ks < 4; ks++) {
                uint32_t a[4][4], b[4][4];
#pragma unroll
                for (int mt = 0; mt < 4; mt++)
                    ldsm4(a[mt], bA + sw128r(aRow[mt], ks * 2 + ldCh));
#pragma unroll
                for (int p = 0; p < 4; p++)
                    ldsm4(b[p], bB + sw128r(bRow[p], ks * 2 + ldCh));
#pragma unroll
                for (int mt = 0; mt < 4; mt++)
#pragma unroll
                    for (int p = 0; p < 4; p++) {
                        mma_f16(acc[mt][2 * p],     a[mt], b[p][0], b[p][2]);
                        mma_f16(acc[mt][2 * p + 1], a[mt], b[p][1], b[p][3]);
                    }
            }
        }
        if (it < 5) {
            char* A = smem + (((it + 1) & 1) * 32768);
            char* B = A + 16384;
#pragma unroll
            for (int u = 0; u < 16; u++) {
                int idx = tid + u * 128, row = idx >> 4, f4 = idx & 15;
                *(uint2*)(A + sw128r(row, f4 >> 1) + (f4 & 1) * 8) = sa[u];
            }
#pragma unroll
            for (int u = 0; u < 8; u++) {
                int idx = tid + u * 128, row = idx >> 3, ch = idx & 7;
                *(int4*)(B + sw128r(row, ch)) = sb[u];
            }
        }
        __syncthreads();
    }

    const int gid = lane >> 2, tig = lane & 3;
    float* outb = out + (size_t)(tok0 >> 12) * Cdim * Ndim;
    const int nb = (tok0 & 4095) + warp_n * 64 + 2 * tig;
#pragma unroll
    for (int mt = 0; mt < 4; mt++) {
        int r = j0 + warp_m * 64 + mt * 16 + gid;
        float bi0 = __ldg(&bias[r]), bi1 = __ldg(&bias[r + 8]);
#pragma unroll
        for (int nt = 0; nt < 8; nt++) {
            int cc = nb + nt * 8;
            *(float2*)(&outb[(size_t)r * Ndim + cc]) =
                make_float2(acc[mt][nt][0] + bi0, acc[mt][nt][1] + bi0);
            *(float2*)(&outb[(size_t)(r + 8) * Ndim + cc]) =
                make_float2(acc[mt][nt][2] + bi1, acc[mt][nt][3] + bi1);
        }
    }
}

// ---------------------------------------------------------------------------
extern "C" void kernel_launch(void* const* d_in, const int* in_sizes, int n_in,
                              void* d_out, int out_size) {
    const float* x      = (const float*)d_in[0];
    const float* qkv_w  = (const float*)d_in[1];
    const float* proj_w = (const float*)d_in[2];
    const float* proj_b = (const float*)d_in[3];
    float* out = (float*)d_out;

    const int smem_gemm = 65536;   // 2 x (16K A + 16K B)
    const int smem_attn = 26624;   // Q6K + K6K + V6K + P8K
    cudaFuncSetAttribute(qkv_mma,  cudaFuncAttributeMaxDynamicSharedMemorySize, smem_gemm);
    cudaFuncSetAttribute(proj_mma, cudaFuncAttributeMaxDynamicSharedMemorySize, smem_gemm);
    cudaFuncSetAttribute(attn_mma, cudaFuncAttributeMaxDynamicSharedMemorySize, smem_attn);

    qkv_mma<<<dim3(9, 512), 128, smem_gemm>>>(x, qkv_w);
    attn_mma<<<8192, 128, smem_attn>>>();
    proj_mma<<<dim3(3, 512), 128, smem_gemm>>>(proj_w, proj_b, out);
}

// round 7
// speedup vs baseline: 8.9762x; 1.3802x over previous
#include <cuda_runtime.h>
#include <cuda_fp16.h>
#include <cstdint>

#define Bq    16
#define Cdim  384
#define Ndim  4096
#define NH    8
#define HD    48
#define OC    1152
#define TOK   65536

// Scratch (__device__ globals: allocation-free rule)
__device__ __half g_xh[(size_t)Bq * Cdim * Ndim];  // fp16 copy of x  [B][C][N]
__device__ __half g_wq[OC * Cdim];                 // fp16 qkv_w
__device__ __half g_wp[Cdim * Cdim];               // fp16 proj_w
__device__ __half g_qkvT[(size_t)OC * TOK];        // [3C][tokens]
__device__ __half g_attn[(size_t)TOK * Cdim];      // [tokens][C]

// ---------------------------------------------------------------------------
// helpers
// ---------------------------------------------------------------------------
__device__ __forceinline__ uint32_t smem_u32(const void* p) {
    uint32_t a; asm("{ .reg .u64 t; cvta.to.shared.u64 t, %1; cvt.u32.u64 %0, t; }" : "=r"(a) : "l"(p));
    return a;
}
__device__ __forceinline__ void ldsm4(uint32_t* r, uint32_t addr) {
    asm volatile("ldmatrix.sync.aligned.m8n8.x4.shared.b16 {%0,%1,%2,%3}, [%4];"
                 : "=r"(r[0]), "=r"(r[1]), "=r"(r[2]), "=r"(r[3]) : "r"(addr));
}
__device__ __forceinline__ void ldsm4t(uint32_t* r, uint32_t addr) {
    asm volatile("ldmatrix.sync.aligned.m8n8.x4.trans.shared.b16 {%0,%1,%2,%3}, [%4];"
                 : "=r"(r[0]), "=r"(r[1]), "=r"(r[2]), "=r"(r[3]) : "r"(addr));
}
__device__ __forceinline__ void mma_f16(float* d, const uint32_t* a, const uint32_t b0,
                                        const uint32_t b1) {
    asm volatile("mma.sync.aligned.m16n8k16.row.col.f32.f16.f16.f32 "
                 "{%0,%1,%2,%3}, {%4,%5,%6,%7}, {%8,%9}, {%0,%1,%2,%3};"
                 : "+f"(d[0]), "+f"(d[1]), "+f"(d[2]), "+f"(d[3])
                 : "r"(a[0]), "r"(a[1]), "r"(a[2]), "r"(a[3]), "r"(b0), "r"(b1));
}
__device__ __forceinline__ uint32_t sw128r(int row, int chunk) {
    return (uint32_t)(row * 128 + ((chunk ^ (row & 7)) << 4));
}
__device__ __forceinline__ uint32_t sw256r(int row, int chunk) {
    return (uint32_t)(row * 256 + ((chunk ^ (row & 7)) << 4));
}
__device__ __forceinline__ uint32_t pack2(float x, float y) {
    uint32_t r;
    asm("cvt.rn.f16x2.f32 %0, %1, %2;" : "=r"(r) : "f"(y), "f"(x));
    return r;
}
#define CP_ASYNC16(dst, src) \
    asm volatile("cp.async.cg.shared.global [%0], [%1], 16;" :: "r"(dst), "l"(src))
#define CP_COMMIT() asm volatile("cp.async.commit_group;" ::: "memory")
#define CP_WAIT1()  asm volatile("cp.async.wait_group 1;" ::: "memory")
#define CP_WAIT0()  asm volatile("cp.async.wait_group 0;" ::: "memory")

// ---------------------------------------------------------------------------
// Kernel 0: fp32 -> fp16 conversion of x, qkv_w, proj_w
// ---------------------------------------------------------------------------
__global__ __launch_bounds__(256) void cvt_inputs(const float* __restrict__ x,
                                                  const float* __restrict__ wq,
                                                  const float* __restrict__ wp) {
    const size_t N4x = (size_t)Bq * Cdim * Ndim / 4;   // 6291456
    const size_t N4q = (size_t)OC * Cdim / 4;          // 110592
    const size_t N4p = (size_t)Cdim * Cdim / 4;        // 36864
    size_t i = (size_t)blockIdx.x * 256 + threadIdx.x;
    if (i < N4x) {
        float4 v = ((const float4*)x)[i];
        ((uint2*)g_xh)[i] = make_uint2(pack2(v.x, v.y), pack2(v.z, v.w));
    } else if (i < N4x + N4q) {
        size_t j = i - N4x;
        float4 v = ((const float4*)wq)[j];
        ((uint2*)g_wq)[j] = make_uint2(pack2(v.x, v.y), pack2(v.z, v.w));
    } else if (i < N4x + N4q + N4p) {
        size_t j = i - N4x - N4q;
        float4 v = ((const float4*)wp)[j];
        ((uint2*)g_wp)[j] = make_uint2(pack2(v.x, v.y), pack2(v.z, v.w));
    }
}

// ---------------------------------------------------------------------------
// Kernel 1: g_qkvT[j][tok] = sum_k g_wq[j][k] * g_xh[b][k][n]
// 128 thr, CTA tile 128x128, BK=64, warp tile 64x64, cp.async 3-stage.
// Stage: A[128 j][64 k] 16KB (128B rows) + B[64 k][128 tok] 16KB (256B rows).
// ---------------------------------------------------------------------------
__global__ __launch_bounds__(128, 2) void qkv_mma() {
    extern __shared__ char smem[];
    const uint32_t sbase = smem_u32(smem);
    const int tid = threadIdx.x, lane = tid & 31, wid = tid >> 5;
    const int warp_m = wid >> 1, warp_n = wid & 1;
    const int j0 = blockIdx.x * 128;
    const int tok0 = blockIdx.y * 128;
    const int n0 = tok0 & 4095;
    const __half* xb = g_xh + (size_t)(tok0 >> 12) * Cdim * Ndim;

    const int aRowL = ((lane >> 3) & 1) * 8 + (lane & 7);
    const int ldCh = lane >> 4;
    int aRow[4];
#pragma unroll
    for (int mt = 0; mt < 4; mt++) aRow[mt] = warp_m * 64 + mt * 16 + aRowL;

    float acc[4][8][4];
#pragma unroll
    for (int i = 0; i < 4; i++)
#pragma unroll
        for (int j = 0; j < 8; j++)
#pragma unroll
            for (int q = 0; q < 4; q++) acc[i][j][q] = 0.f;

    // per-thread fill coordinates (8 chunks A + 8 chunks B per stage)
    const int aFr = tid >> 3, aFc = tid & 7;        // A row stepped by 16
    const int bFr = tid >> 4, bFc = tid & 15;       // B krow stepped by 8

    auto fill = [&](int s, int t) {
        const int kt = t * 64;
        const uint32_t A = sbase + (uint32_t)s * 32768u;
        const uint32_t B = A + 16384u;
#pragma unroll
        for (int u = 0; u < 8; u++) {
            int row = aFr + u * 16;
            CP_ASYNC16(A + sw128r(row, aFc), g_wq + (size_t)(j0 + row) * Cdim + kt + aFc * 8);
        }
#pragma unroll
        for (int u = 0; u < 8; u++) {
            int krow = bFr + u * 8;
            CP_ASYNC16(B + sw256r(krow, bFc), xb + (size_t)(kt + krow) * Ndim + n0 + bFc * 8);
        }
        CP_COMMIT();
    };

    fill(0, 0);
    fill(1, 1);

    for (int it = 0; it < 6; it++) {
        if (it < 5) CP_WAIT1(); else CP_WAIT0();
        __syncthreads();
        // compute stage it%3
        {
            const uint32_t bA = sbase + (uint32_t)(it % 3) * 32768u;
            const uint32_t bB = bA + 16384u;
#pragma unroll
            for (int ks = 0; ks < 4; ks++) {
                uint32_t a[4][4], b[4][4];
#pragma unroll
                for (int mt = 0; mt < 4; mt++)
                    ldsm4(a[mt], bA + sw128r(aRow[mt], ks * 2 + ldCh));
#pragma unroll
                for (int p = 0; p < 4; p++) {
                    int krow = ks * 16 + aRowL;
                    ldsm4t(b[p], bB + sw256r(krow, warp_n * 8 + p * 2 + ldCh));
                }
#pragma unroll
                for (int mt = 0; mt < 4; mt++)
#pragma unroll
                    for (int p = 0; p < 4; p++) {
                        mma_f16(acc[mt][2 * p],     a[mt], b[p][0], b[p][1]);
                        mma_f16(acc[mt][2 * p + 1], a[mt], b[p][2], b[p][3]);
                    }
            }
        }
        if (it + 2 < 6) fill((it + 2) % 3, it + 2);
    }

    const int gid = lane >> 2, tig = lane & 3;
#pragma unroll
    for (int mt = 0; mt < 4; mt++) {
        int r = j0 + warp_m * 64 + mt * 16 + gid;
        size_t r0o = (size_t)r * TOK, r1o = (size_t)(r + 8) * TOK;
        int cb = tok0 + warp_n * 64 + 2 * tig;
#pragma unroll
        for (int nt = 0; nt < 8; nt++) {
            int cc = cb + nt * 8;
            *(uint32_t*)(&g_qkvT[r0o + cc]) = pack2(acc[mt][nt][0], acc[mt][nt][1]);
            *(uint32_t*)(&g_qkvT[r1o + cc]) = pack2(acc[mt][nt][2], acc[mt][nt][3]);
        }
    }
}

// ---------------------------------------------------------------------------
// Kernel 2: block-local attention, fp16 mma. 1 CTA (128 thr) per (b,h,chunk).
// Smem (half): Qs[48][64]@0, Ks@6144, Vs@12288, Ps[64][64]@18432.
// ---------------------------------------------------------------------------
__global__ __launch_bounds__(128) void attn_mma() {
    extern __shared__ char smem[];
    const uint32_t sbase = smem_u32(smem);
    const int tid = threadIdx.x, lane = tid & 31, w = tid >> 5;
    const int blk = blockIdx.x;
    const int b = blk >> 9, h = (blk >> 6) & 7, nc = blk & 63;
    const size_t m0 = (size_t)b * Ndim + nc * 64;
    const __half* qg = g_qkvT + (size_t)(h * HD) * TOK + m0;

#pragma unroll
    for (int t = 0; t < 3; t++) {
        const __half* src = qg + (size_t)t * Cdim * TOK;
        char* dst = smem + t * 6144;
#pragma unroll
        for (int e = 0; e < 3; e++) {
            int idx = tid + e * 128;
            int row = idx >> 3, ch = idx & 7;
            *(int4*)(dst + sw128r(row, ch)) = *(const int4*)(src + (size_t)row * TOK + ch * 8);
        }
    }
    __syncthreads();

    const int aRowL = ((lane >> 3) & 1) * 8 + (lane & 7);
    const int ldCh = lane >> 4;

    float s[8][4];
#pragma unroll
    for (int j = 0; j < 8; j++)
#pragma unroll
        for (int q = 0; q < 4; q++) s[j][q] = 0.f;
#pragma unroll
    for (int ks = 0; ks < 3; ks++) {
        uint32_t ar[4], a[4], kb[4][4];
        int drow = ks * 16 + aRowL;
        ldsm4t(ar, sbase + sw128r(drow, w * 2 + ldCh));
        a[0] = ar[0]; a[1] = ar[2]; a[2] = ar[1]; a[3] = ar[3];
#pragma unroll
        for (int p = 0; p < 4; p++)
            ldsm4t(kb[p], sbase + 6144u + sw128r(drow, p * 2 + ldCh));
#pragma unroll
        for (int p = 0; p < 4; p++) {
            mma_f16(s[2 * p],     a, kb[p][0], kb[p][1]);
            mma_f16(s[2 * p + 1], a, kb[p][2], kb[p][3]);
        }
    }

    const int gid = lane >> 2, tig = lane & 3;
    const float scale = 0.14433756729740643f;
    {
        float m0v = -1e30f, m1v = -1e30f;
#pragma unroll
        for (int nt = 0; nt < 8; nt++) {
#pragma unroll
            for (int q = 0; q < 4; q++) s[nt][q] *= scale;
            m0v = fmaxf(m0v, fmaxf(s[nt][0], s[nt][1]));
            m1v = fmaxf(m1v, fmaxf(s[nt][2], s[nt][3]));
        }
#pragma unroll
        for (int o = 1; o <= 2; o <<= 1) {
            m0v = fmaxf(m0v, __shfl_xor_sync(~0u, m0v, o));
            m1v = fmaxf(m1v, __shfl_xor_sync(~0u, m1v, o));
        }
        float s0 = 0.f, s1 = 0.f;
#pragma unroll
        for (int nt = 0; nt < 8; nt++) {
            s[nt][0] = __expf(s[nt][0] - m0v); s[nt][1] = __expf(s[nt][1] - m0v);
            s[nt][2] = __expf(s[nt][2] - m1v); s[nt][3] = __expf(s[nt][3] - m1v);
            s0 += s[nt][0] + s[nt][1]; s1 += s[nt][2] + s[nt][3];
        }
#pragma unroll
        for (int o = 1; o <= 2; o <<= 1) {
            s0 += __shfl_xor_sync(~0u, s0, o);
            s1 += __shfl_xor_sync(~0u, s1, o);
        }
        float i0 = 1.f / s0, i1 = 1.f / s1;
        const int r0 = w * 16 + gid, r1 = r0 + 8;
        char* Ps = smem + 18432;
#pragma unroll
        for (int nt = 0; nt < 8; nt++) {
            *(uint32_t*)(Ps + sw128r(r0, nt) + tig * 4) = pack2(s[nt][0] * i0, s[nt][1] * i0);
            *(uint32_t*)(Ps + sw128r(r1, nt) + tig * 4) = pack2(s[nt][2] * i1, s[nt][3] * i1);
        }
    }
    __syncwarp();

    float o[6][4];
#pragma unroll
    for (int j = 0; j < 6; j++)
#pragma unroll
        for (int q = 0; q < 4; q++) o[j][q] = 0.f;
#pragma unroll
    for (int ks = 0; ks < 4; ks++) {
        uint32_t a[4], vb[3][4];
        ldsm4(a, sbase + 18432u + sw128r(w * 16 + aRowL, ks * 2 + ldCh));
#pragma unroll
        for (int p = 0; p < 3; p++)
            ldsm4(vb[p], sbase + 12288u + sw128r(p * 16 + aRowL, ks * 2 + ldCh));
#pragma unroll
        for (int p = 0; p < 3; p++) {
            mma_f16(o[2 * p],     a, vb[p][0], vb[p][2]);
            mma_f16(o[2 * p + 1], a, vb[p][1], vb[p][3]);
        }
    }
    {
        const int r0 = w * 16 + gid;
#pragma unroll
        for (int nt = 0; nt < 6; nt++) {
            int col = h * HD + nt * 8 + tig * 2;
            *(uint32_t*)(&g_attn[(m0 + r0) * Cdim + col])     = pack2(o[nt][0], o[nt][1]);
            *(uint32_t*)(&g_attn[(m0 + r0 + 8) * Cdim + col]) = pack2(o[nt][2], o[nt][3]);
        }
    }
}

// ---------------------------------------------------------------------------
// Kernel 3: out[b][c][n] = sum_k g_wp[c][k] * g_attn[tok][k] + bias[c]
// cp.async 3-stage; A[128 c][64 k], B[128 tok][64 k] both 128B rows.
// ---------------------------------------------------------------------------
__global__ __launch_bounds__(128, 2) void proj_mma(const float* __restrict__ bias,
                                                   float* __restrict__ out) {
    extern __shared__ char smem[];
    const uint32_t sbase = smem_u32(smem);
    const int tid = threadIdx.x, lane = tid & 31, wid = tid >> 5;
    const int warp_m = wid >> 1, warp_n = wid & 1;
    const int j0 = blockIdx.x * 128;
    const int tok0 = blockIdx.y * 128;

    const int aRowL = ((lane >> 3) & 1) * 8 + (lane & 7);
    const int ldCh = lane >> 4;
    int aRow[4], bRow[4];
#pragma unroll
    for (int mt = 0; mt < 4; mt++) aRow[mt] = warp_m * 64 + mt * 16 + aRowL;
#pragma unroll
    for (int p = 0; p < 4; p++)    bRow[p] = warp_n * 64 + p * 16 + aRowL;

    float acc[4][8][4];
#pragma unroll
    for (int i = 0; i < 4; i++)
#pragma unroll
        for (int j = 0; j < 8; j++)
#pragma unroll
            for (int q = 0; q < 4; q++) acc[i][j][q] = 0.f;

    const int fR = tid >> 3, fC = tid & 7;
    auto fill = [&](int s, int t) {
        const int kt = t * 64;
        const uint32_t A = sbase + (uint32_t)s * 32768u;
        const uint32_t B = A + 16384u;
#pragma unroll
        for (int u = 0; u < 8; u++) {
            int row = fR + u * 16;
            CP_ASYNC16(A + sw128r(row, fC), g_wp + (size_t)(j0 + row) * Cdim + kt + fC * 8);
            CP_ASYNC16(B + sw128r(row, fC),
                       g_attn + (size_t)(tok0 + row) * Cdim + kt + fC * 8);
        }
        CP_COMMIT();
    };

    fill(0, 0);
    fill(1, 1);

    for (int it = 0; it < 6; it++) {
        if (it < 5) CP_WAIT1(); else CP_WAIT0();
        __syncthreads();
        {
            const uint32_t bA = sbase + (uint32_t)(it % 3) * 32768u;
            const uint32_t bB = bA + 16384u;
#pragma unroll
            for (int ks = 0; ks < 4; ks++) {
                uint32_t a[4][4], b[4][4];
#pragma unroll
                for (int mt = 0; mt < 4; mt++)
                    ldsm4(a[mt], bA + sw128r(aRow[mt], ks * 2 + ldCh));
#pragma unroll
                for (int p = 0; p < 4; p++)
                    ldsm4(b[p], bB + sw128r(bRow[p], ks * 2 + ldCh));
#pragma unroll
                for (int mt = 0; mt < 4; mt++)
#pragma unroll
                    for (int p = 0; p < 4; p++) {
                        mma_f16(acc[mt][2 * p],     a[mt], b[p][0], b[p][2]);
                        mma_f16(acc[mt][2 * p + 1], a[mt], b[p][1], b[p][3]);
                    }
            }
        }
        if (it + 2 < 6) fill((it + 2) % 3, it + 2);
    }

    const int gid = lane >> 2, tig = lane & 3;
    float* outb = out + (size_t)(tok0 >> 12) * Cdim * Ndim;
    const int nb = (tok0 & 4095) + warp_n * 64 + 2 * tig;
#pragma unroll
    for (int mt = 0; mt < 4; mt++) {
        int r = j0 + warp_m * 64 + mt * 16 + gid;
        float bi0 = __ldg(&bias[r]), bi1 = __ldg(&bias[r + 8]);
#pragma unroll
        for (int nt = 0; nt < 8; nt++) {
            int cc = nb + nt * 8;
            *(float2*)(&outb[(size_t)r * Ndim + cc]) =
                make_float2(acc[mt][nt][0] + bi0, acc[mt][nt][1] + bi0);
            *(float2*)(&outb[(size_t)(r + 8) * Ndim + cc]) =
                make_float2(acc[mt][nt][2] + bi1, acc[mt][nt][3] + bi1);
        }
    }
}

// ---------------------------------------------------------------------------
extern "C" void kernel_launch(void* const* d_in, const int* in_sizes, int n_in,
                              void* d_out, int out_size) {
    const float* x      = (const float*)d_in[0];
    const float* qkv_w  = (const float*)d_in[1];
    const float* proj_w = (const float*)d_in[2];
    const float* proj_b = (const float*)d_in[3];
    float* out = (float*)d_out;

    const int smem_gemm = 98304;   // 3 stages x 32KB
    const int smem_attn = 26624;
    cudaFuncSetAttribute(qkv_mma,  cudaFuncAttributeMaxDynamicSharedMemorySize, smem_gemm);
    cudaFuncSetAttribute(proj_mma, cudaFuncAttributeMaxDynamicSharedMemorySize, smem_gemm);
    cudaFuncSetAttribute(attn_mma, cudaFuncAttributeMaxDynamicSharedMemorySize, smem_attn);

    const size_t n4 = (size_t)Bq * Cdim * Ndim / 4 + (size_t)OC * Cdim / 4
                    + (size_t)Cdim * Cdim / 4;
    cvt_inputs<<<(int)((n4 + 255) / 256), 256>>>(x, qkv_w, proj_w);
    qkv_mma<<<dim3(9, 512), 128, smem_gemm>>>();
    attn_mma<<<8192, 128, smem_attn>>>();
    proj_mma<<<dim3(3, 512), 128, smem_gemm>>>(proj_b, out);
}